// round 1
// baseline (speedup 1.0000x reference)
#include <cuda_runtime.h>
#include <cstdint>

// ---------------------------------------------------------------------------
// BarrierNet fused MLP + CBF filter, fp32, f32x2-packed (2 rows / thread).
//
// Layers: obs[B,10] -> silu(W1 10->128) -> {silu(W21 128->32), silu(W22 128->32)}
//         -> unom = x21@W31^T+b31 (2), alpha = 4*sigmoid(x22@W32^T+b32)
//         -> CBF projection epilogue.
//
// Weights are stored DUPLICATED (w,w) as float2 in dynamic shared memory so a
// single 8B LDS yields a packed f32x2 operand; all matmul FMAs are
// fma.rn.f32x2 (FFMA2), doubling effective fp32 throughput on sm_103a.
// ---------------------------------------------------------------------------

typedef unsigned long long u64;

__device__ __forceinline__ u64 pk2(float lo, float hi) {
    u64 r;
    asm("mov.b64 %0, {%1, %2};" : "=l"(r) : "f"(lo), "f"(hi));
    return r;
}
__device__ __forceinline__ void upk2(u64 v, float& lo, float& hi) {
    asm("mov.b64 {%0, %1}, %2;" : "=f"(lo), "=f"(hi) : "l"(v));
}
__device__ __forceinline__ u64 fma2(u64 a, u64 b, u64 c) {
    u64 d;
    asm("fma.rn.f32x2 %0, %1, %2, %3;" : "=l"(d) : "l"(a), "l"(b), "l"(c));
    return d;
}

__device__ __forceinline__ float fast_silu(float z) {
    // z * sigmoid(z) = z / (1 + exp(-z));  __expf -> MUFU EX2, __fdividef -> MUFU RCP
    return __fdividef(z, 1.0f + __expf(-z));
}
__device__ __forceinline__ float fast_sigmoid(float z) {
    return __fdividef(1.0f, 1.0f + __expf(-z));
}

// ---- shared-memory layout (float2 units unless noted) ----
// W1d  : [128][10] dup           @ 0      (1280)
// b1d  : [128]     dup           @ 1280   (128)
// W21d : [128 j][32 k] dup       @ 1408   (4096)
// W22d : [128 j][32 k] dup       @ 5504   (4096)
// b21d : [32] dup                @ 9600   (32)
// b22d : [32] dup                @ 9632   (32)
// ---- scalar float tail (float units, base = 9664*2 = 19328) ----
// W31  : [2][32]                 @ f19328 (64)
// b31  : [2]                     @ f19392 (2)
// W32  : [32]                    @ f19394 (32)
// b32  : [1]                     @ f19426 (1)
#define F2_W1   0
#define F2_B1   1280
#define F2_W21  1408
#define F2_W22  5504
#define F2_B21  9600
#define F2_B22  9632
#define FT_W31  19328
#define FT_B31  19392
#define FT_W32  19394
#define FT_B32  19426
#define SMEM_BYTES ((19427) * 4)   // 77708 B

__device__ __forceinline__ void cbf_project(
    float u0, float u1, float alpha_pre,
    float rx, float ry, float vhx, float vhy,
    float& ox, float& oy)
{
    float alpha   = 4.0f * fast_sigmoid(alpha_pre);
    float barrier = rx * rx + ry * ry - 0.64f;           // R_SAFE^2 = 0.64
    float lf      = -2.0f * (rx * vhx + ry * vhy);
    float Gx = -2.0f * rx, Gy = -2.0f * ry;
    float h   = lf + alpha * barrier;
    float gg  = Gx * Gx + Gy * Gy;
    float viol = Gx * u0 + Gy * u1 - h;
    float lam = (gg > 0.0f)
        ? __fdividef(fmaxf(viol, 0.0f), fmaxf(gg, 1e-12f))
        : 0.0f;
    ox = u0 - lam * Gx;
    oy = u1 - lam * Gy;
}

__global__ void __launch_bounds__(256)
barriernet_kernel(const float* __restrict__ obs,
                  const float* __restrict__ W1,  const float* __restrict__ b1,
                  const float* __restrict__ W21, const float* __restrict__ b21,
                  const float* __restrict__ W22, const float* __restrict__ b22,
                  const float* __restrict__ W31, const float* __restrict__ b31,
                  const float* __restrict__ W32, const float* __restrict__ b32,
                  float* __restrict__ out, int B)
{
    extern __shared__ float2 sm2[];
    float* smf = reinterpret_cast<float*>(sm2);
    const int tid = threadIdx.x;

    // ---- cooperative weight staging (duplicated lanes) ----
    for (int i = tid; i < 1280; i += 256) {            // W1 [128,10] row-major
        float w = W1[i];
        sm2[F2_W1 + i] = make_float2(w, w);
    }
    for (int i = tid; i < 128; i += 256) {
        float v = b1[i];
        sm2[F2_B1 + i] = make_float2(v, v);
    }
    for (int i = tid; i < 4096; i += 256) {            // W21 [32,128] -> [j][k]
        int j = i >> 5, k = i & 31;
        float w = W21[k * 128 + j];
        sm2[F2_W21 + i] = make_float2(w, w);
    }
    for (int i = tid; i < 4096; i += 256) {
        int j = i >> 5, k = i & 31;
        float w = W22[k * 128 + j];
        sm2[F2_W22 + i] = make_float2(w, w);
    }
    if (tid < 32) {
        float v21 = b21[tid], v22 = b22[tid];
        sm2[F2_B21 + tid] = make_float2(v21, v21);
        sm2[F2_B22 + tid] = make_float2(v22, v22);
    }
    if (tid < 64) smf[FT_W31 + tid] = W31[tid];        // [2][32] row-major
    if (tid < 2)  smf[FT_B31 + tid] = b31[tid];
    if (tid < 32) smf[FT_W32 + tid] = W32[tid];
    if (tid == 0) smf[FT_B32] = b32[0];
    __syncthreads();

    const long long gid = (long long)blockIdx.x * 256 + tid;
    const long long r0  = gid * 2;                     // rows r0, r0+1
    if (r0 >= B) return;

    // ---- load two obs rows (80 contiguous, 16B-aligned bytes) ----
    const float4* op = reinterpret_cast<const float4*>(obs + r0 * 10);
    float4 q0 = op[0], q1 = op[1], q2 = op[2], q3 = op[3], q4 = op[4];
    u64 o[10];
    o[0] = pk2(q0.x, q2.z); o[1] = pk2(q0.y, q2.w);
    o[2] = pk2(q0.z, q3.x); o[3] = pk2(q0.w, q3.y);
    o[4] = pk2(q1.x, q3.z); o[5] = pk2(q1.y, q3.w);
    o[6] = pk2(q1.z, q4.x); o[7] = pk2(q1.w, q4.y);
    o[8] = pk2(q2.x, q4.z); o[9] = pk2(q2.y, q4.w);

    // ---- packed accumulators for the two 32-wide hidden layers ----
    u64 a21[32], a22[32];
    {
        const u64* pb21 = reinterpret_cast<const u64*>(sm2 + F2_B21);
        const u64* pb22 = reinterpret_cast<const u64*>(sm2 + F2_B22);
        #pragma unroll
        for (int k = 0; k < 32; k++) { a21[k] = pb21[k]; a22[k] = pb22[k]; }
    }

    const u64* sW1  = reinterpret_cast<const u64*>(sm2 + F2_W1);
    const u64* sB1  = reinterpret_cast<const u64*>(sm2 + F2_B1);
    const u64* sW21 = reinterpret_cast<const u64*>(sm2 + F2_W21);
    const u64* sW22 = reinterpret_cast<const u64*>(sm2 + F2_W22);

    // ---- main loop: layer-1 column j consumed immediately into both branches
    #pragma unroll 1
    for (int j = 0; j < 128; j++) {
        const u64* w1 = sW1 + j * 10;
        u64 z = sB1[j];
        #pragma unroll
        for (int f = 0; f < 10; f++) z = fma2(o[f], w1[f], z);

        float zl, zh; upk2(z, zl, zh);
        u64 x = pk2(fast_silu(zl), fast_silu(zh));

        const u64* w21 = sW21 + j * 32;
        const u64* w22 = sW22 + j * 32;
        #pragma unroll
        for (int k = 0; k < 32; k++) {
            a21[k] = fma2(x, w21[k], a21[k]);
            a22[k] = fma2(x, w22[k], a22[k]);
        }
    }

    // ---- heads: silu(a21)@W31^T + b31, silu(a22)@W32^T + b32 (both lanes) ----
    float u0l = smf[FT_B31],     u0h = smf[FT_B31];
    float u1l = smf[FT_B31 + 1], u1h = smf[FT_B31 + 1];
    float awl = smf[FT_B32],     awh = smf[FT_B32];
    #pragma unroll
    for (int k = 0; k < 32; k++) {
        float sl, sh; upk2(a21[k], sl, sh);
        sl = fast_silu(sl); sh = fast_silu(sh);
        float w0 = smf[FT_W31 + k];
        float w1w = smf[FT_W31 + 32 + k];
        u0l += sl * w0;  u0h += sh * w0;
        u1l += sl * w1w; u1h += sh * w1w;

        float tl, th; upk2(a22[k], tl, th);
        tl = fast_silu(tl); th = fast_silu(th);
        float ww = smf[FT_W32 + k];
        awl += tl * ww; awh += th * ww;
    }

    // ---- CBF epilogue per row ----
    float rxl, rxh, ryl, ryh, vxl, vxh, vyl, vyh;
    upk2(o[6], rxl, rxh); upk2(o[7], ryl, ryh);
    upk2(o[8], vxl, vxh); upk2(o[9], vyl, vyh);

    float o0x, o0y, o1x, o1y;
    cbf_project(u0l, u1l, awl, rxl, ryl, vxl, vyl, o0x, o0y);
    cbf_project(u0h, u1h, awh, rxh, ryh, vxh, vyh, o1x, o1y);

    float4 res = make_float4(o0x, o0y, o1x, o1y);
    *reinterpret_cast<float4*>(out + r0 * 2) = res;
}

extern "C" void kernel_launch(void* const* d_in, const int* in_sizes, int n_in,
                              void* d_out, int out_size)
{
    const float* obs = (const float*)d_in[0];
    const float* W1  = (const float*)d_in[1];
    const float* b1  = (const float*)d_in[2];
    const float* W21 = (const float*)d_in[3];
    const float* b21 = (const float*)d_in[4];
    const float* W22 = (const float*)d_in[5];
    const float* b22 = (const float*)d_in[6];
    const float* W31 = (const float*)d_in[7];
    const float* b31 = (const float*)d_in[8];
    const float* W32 = (const float*)d_in[9];
    const float* b32 = (const float*)d_in[10];
    float* out = (float*)d_out;

    int B = in_sizes[0] / 10;

    cudaFuncSetAttribute(barriernet_kernel,
                         cudaFuncAttributeMaxDynamicSharedMemorySize, SMEM_BYTES);

    int rows_per_block = 256 * 2;
    int blocks = (B + rows_per_block - 1) / rows_per_block;
    barriernet_kernel<<<blocks, 256, SMEM_BYTES>>>(
        obs, W1, b1, W21, b21, W22, b22, W31, b31, W32, b32, out, B);
}

// round 2
// speedup vs baseline: 1.3009x; 1.3009x over previous
#include <cuda_runtime.h>

// ---------------------------------------------------------------------------
// BarrierNet fused MLP + CBF filter — register-tiled f32x2 GEMM version.
//
// Block = 256 threads handles 256 rows (128 row-pairs packed into f32x2).
//   Stage : all weights into SMEM (duplicated (w,w) pairs for f32x2 FMA).
//   Phase A: x = silu(obs @ W1^T + b1), stored to SMEM as x2[j][rowpair] u64.
//   Phase B: hidden = x @ W2 (W2 = [W21|W22], 128x64), each thread computes an
//            8-row x 8-k register tile -> 6 LDS.128 per 32 FFMA2.
//   Phase C: silu(hidden) -> heads (u0,u1,alpha) -> CBF projection -> out.
// ---------------------------------------------------------------------------

typedef unsigned long long u64;

__device__ __forceinline__ u64 pk2(float lo, float hi) {
    u64 r; asm("mov.b64 %0, {%1, %2};" : "=l"(r) : "f"(lo), "f"(hi)); return r;
}
__device__ __forceinline__ void upk2(u64 v, float& lo, float& hi) {
    asm("mov.b64 {%0, %1}, %2;" : "=f"(lo), "=f"(hi) : "l"(v));
}
__device__ __forceinline__ u64 fma2(u64 a, u64 b, u64 c) {
    u64 d; asm("fma.rn.f32x2 %0, %1, %2, %3;" : "=l"(d) : "l"(a), "l"(b), "l"(c)); return d;
}
__device__ __forceinline__ u64 dup2(float w) { return pk2(w, w); }

__device__ __forceinline__ float fast_silu(float z) {
    return __fdividef(z, 1.0f + __expf(-z));
}
__device__ __forceinline__ float fast_sigmoid(float z) {
    return __fdividef(1.0f, 1.0f + __expf(-z));
}

// ---- shared memory layout (u64 units) ----
#define OFF_W1D  0        // [128 j][10 f] dup            (1280)
#define OFF_B1D  1280     // [128] dup                    (128)
#define OFF_B2D  1408     // [64] dup (b21|b22)           (64)
#define OFF_W31D 1472     // [2][32] dup                  (64)
#define OFF_W32D 1536     // [32] dup                     (32)
#define OFF_SCAL 1568     // floats: b31[0],b31[1],b32    (2 u64 slots)
#define OFF_W2D  1576     // [128 j][64 k] dup            (8192)
#define OFF_X2   9768     // [128 j][128 rp] u64          (16384)
#define OFF_H2   9768     // aliased over X2: [128 rp][stride 66] (8448)
#define SMEM_U64 (9768 + 16384)
#define SMEM_BYTES (SMEM_U64 * 8)   // 209216 B

__device__ __forceinline__ void cbf_project(
    float u0, float u1, float alpha_pre,
    float rx, float ry, float vhx, float vhy,
    float& ox, float& oy)
{
    float alpha   = 4.0f * fast_sigmoid(alpha_pre);
    float barrier = rx * rx + ry * ry - 0.64f;          // R_SAFE^2
    float lf      = -2.0f * (rx * vhx + ry * vhy);
    float Gx = -2.0f * rx, Gy = -2.0f * ry;
    float h    = lf + alpha * barrier;
    float gg   = Gx * Gx + Gy * Gy;
    float viol = Gx * u0 + Gy * u1 - h;
    float lam  = (gg > 0.0f)
        ? __fdividef(fmaxf(viol, 0.0f), fmaxf(gg, 1e-12f))
        : 0.0f;
    ox = u0 - lam * Gx;
    oy = u1 - lam * Gy;
}

__global__ void __launch_bounds__(256, 1)
barriernet_kernel(const float* __restrict__ obs,
                  const float* __restrict__ W1,  const float* __restrict__ b1,
                  const float* __restrict__ W21, const float* __restrict__ b21,
                  const float* __restrict__ W22, const float* __restrict__ b22,
                  const float* __restrict__ W31, const float* __restrict__ b31,
                  const float* __restrict__ W32, const float* __restrict__ b32,
                  float* __restrict__ out, int B)
{
    extern __shared__ u64 sm[];
    float* smf = reinterpret_cast<float*>(sm);
    const int tid = threadIdx.x;

    // ---------------- weight staging ----------------
    for (int i = tid; i < 1280; i += 256) sm[OFF_W1D + i] = dup2(W1[i]);  // [128,10] row-major
    for (int i = tid; i < 128; i += 256)  sm[OFF_B1D + i] = dup2(b1[i]);
    if (tid < 64) {
        float v = (tid < 32) ? b21[tid] : b22[tid - 32];
        sm[OFF_B2D + tid] = dup2(v);
        sm[OFF_W31D + tid] = dup2(W31[tid]);                              // [2][32] row-major
    }
    if (tid < 32) sm[OFF_W32D + tid] = dup2(W32[tid]);
    if (tid == 0) {
        smf[OFF_SCAL * 2 + 0] = b31[0];
        smf[OFF_SCAL * 2 + 1] = b31[1];
        smf[OFF_SCAL * 2 + 2] = b32[0];
    }
    for (int i = tid; i < 8192; i += 256) {                               // W2d[j][k]
        int j = i >> 6, k = i & 63;
        float w = (k < 32) ? W21[k * 128 + j] : W22[(k - 32) * 128 + j];
        sm[OFF_W2D + i] = dup2(w);
    }
    __syncthreads();

    const long long row_base = (long long)blockIdx.x * 256;

    // ---------------- Phase A: layer 1, x -> SMEM ----------------
    {
        const int rp = tid & 127;          // row-pair id
        const int jh = tid >> 7;           // j-half (0 or 1)
        const long long r0 = row_base + 2 * rp;
        u64 o[10];
        if (r0 < B) {
            const float4* op = reinterpret_cast<const float4*>(obs + r0 * 10);
            float4 q0 = op[0], q1 = op[1], q2 = op[2], q3 = op[3], q4 = op[4];
            o[0] = pk2(q0.x, q2.z); o[1] = pk2(q0.y, q2.w);
            o[2] = pk2(q0.z, q3.x); o[3] = pk2(q0.w, q3.y);
            o[4] = pk2(q1.x, q3.z); o[5] = pk2(q1.y, q3.w);
            o[6] = pk2(q1.z, q4.x); o[7] = pk2(q1.w, q4.y);
            o[8] = pk2(q2.x, q4.z); o[9] = pk2(q2.y, q4.w);
        } else {
            #pragma unroll
            for (int f = 0; f < 10; f++) o[f] = 0ull;
        }
        const u64* w1 = sm + OFF_W1D + jh * 640;   // 64 rows of 10
        const u64* bb = sm + OFF_B1D + jh * 64;
        u64* xo = sm + OFF_X2 + (jh * 64) * 128 + rp;
        #pragma unroll 1
        for (int j = 0; j < 64; j++) {
            const u64* w = w1 + j * 10;
            u64 z = bb[j];
            #pragma unroll
            for (int f = 0; f < 10; f++) z = fma2(o[f], w[f], z);
            float zl, zh; upk2(z, zl, zh);
            xo[j * 128] = pk2(fast_silu(zl), fast_silu(zh));
        }
    }
    __syncthreads();

    // ---------------- Phase B: hidden = x @ W2, 8-row x 8-k tiles ----------------
    const int kg = tid >> 5;     // 0..7   -> k = kg*8 .. kg*8+7
    const int rg = tid & 31;     // 0..31  -> packs {2rg, 2rg+1, 64+2rg, 64+2rg+1}
    const int k0 = kg * 8;

    u64 acc[4][8];
    #pragma unroll
    for (int i = 0; i < 8; i++) {
        u64 b = sm[OFF_B2D + k0 + i];
        acc[0][i] = b; acc[1][i] = b; acc[2][i] = b; acc[3][i] = b;
    }
    {
        const ulonglong2* xbase = reinterpret_cast<const ulonglong2*>(sm + OFF_X2);
        const ulonglong2* wbase = reinterpret_cast<const ulonglong2*>(sm + OFF_W2D);
        #pragma unroll 2
        for (int j = 0; j < 128; j++) {
            ulonglong2 xa = xbase[j * 64 + rg];          // packs 2rg, 2rg+1
            ulonglong2 xb = xbase[j * 64 + 32 + rg];     // packs 64+2rg, 64+2rg+1
            ulonglong2 w0 = wbase[j * 32 + kg * 4 + 0];
            ulonglong2 w1v = wbase[j * 32 + kg * 4 + 1];
            ulonglong2 w2v = wbase[j * 32 + kg * 4 + 2];
            ulonglong2 w3v = wbase[j * 32 + kg * 4 + 3];
            u64 xs[4] = { xa.x, xa.y, xb.x, xb.y };
            u64 ws[8] = { w0.x, w0.y, w1v.x, w1v.y, w2v.x, w2v.y, w3v.x, w3v.y };
            #pragma unroll
            for (int p = 0; p < 4; p++)
                #pragma unroll
                for (int i = 0; i < 8; i++)
                    acc[p][i] = fma2(xs[p], ws[i], acc[p][i]);
        }
    }
    __syncthreads();   // x2 / W2d now dead; safe to overwrite with h2

    // silu(hidden) -> h2[rp][k] (stride 66 to dodge bank conflicts)
    #pragma unroll
    for (int p = 0; p < 4; p++) {
        int rp = (p < 2) ? (2 * rg + p) : (64 + 2 * rg + (p - 2));
        u64* h = sm + OFF_H2 + rp * 66 + k0;
        #pragma unroll
        for (int i = 0; i < 4; i++) {
            float a, b, c, d;
            upk2(acc[p][2 * i],     a, b);
            upk2(acc[p][2 * i + 1], c, d);
            ulonglong2 v;
            v.x = pk2(fast_silu(a), fast_silu(b));
            v.y = pk2(fast_silu(c), fast_silu(d));
            *reinterpret_cast<ulonglong2*>(h + 2 * i) = v;
        }
    }
    __syncthreads();

    // ---------------- Phase C: heads + CBF epilogue (threads 0..127) ----------------
    if (tid < 128) {
        const int rp = tid;
        const long long r0 = row_base + 2 * rp;
        if (r0 < B) {
            const u64* h = sm + OFF_H2 + rp * 66;
            float b31x = smf[OFF_SCAL * 2 + 0];
            float b31y = smf[OFF_SCAL * 2 + 1];
            float b32s = smf[OFF_SCAL * 2 + 2];
            u64 u0 = dup2(b31x), u1 = dup2(b31y), aw = dup2(b32s);
            #pragma unroll
            for (int k = 0; k < 32; k++) {
                u64 s = h[k];
                u0 = fma2(s, sm[OFF_W31D + k],      u0);
                u1 = fma2(s, sm[OFF_W31D + 32 + k], u1);
                u64 t = h[32 + k];
                aw = fma2(t, sm[OFF_W32D + k], aw);
            }
            float u0l, u0h, u1l, u1h, awl, awh;
            upk2(u0, u0l, u0h); upk2(u1, u1l, u1h); upk2(aw, awl, awh);

            const float2* p0 = reinterpret_cast<const float2*>(obs + r0 * 10 + 6);
            float2 a0 = p0[0], v0 = p0[1];
            const float2* p1 = reinterpret_cast<const float2*>(obs + (r0 + 1) * 10 + 6);
            float2 a1 = p1[0], v1 = p1[1];

            float o0x, o0y, o1x, o1y;
            cbf_project(u0l, u1l, awl, a0.x, a0.y, v0.x, v0.y, o0x, o0y);
            cbf_project(u0h, u1h, awh, a1.x, a1.y, v1.x, v1.y, o1x, o1y);

            *reinterpret_cast<float4*>(out + r0 * 2) = make_float4(o0x, o0y, o1x, o1y);
        }
    }
}

extern "C" void kernel_launch(void* const* d_in, const int* in_sizes, int n_in,
                              void* d_out, int out_size)
{
    const float* obs = (const float*)d_in[0];
    const float* W1  = (const float*)d_in[1];
    const float* b1  = (const float*)d_in[2];
    const float* W21 = (const float*)d_in[3];
    const float* b21 = (const float*)d_in[4];
    const float* W22 = (const float*)d_in[5];
    const float* b22 = (const float*)d_in[6];
    const float* W31 = (const float*)d_in[7];
    const float* b31 = (const float*)d_in[8];
    const float* W32 = (const float*)d_in[9];
    const float* b32 = (const float*)d_in[10];
    float* out = (float*)d_out;

    int B = in_sizes[0] / 10;

    cudaFuncSetAttribute(barriernet_kernel,
                         cudaFuncAttributeMaxDynamicSharedMemorySize, SMEM_BYTES);

    int blocks = (B + 255) / 256;
    barriernet_kernel<<<blocks, 256, SMEM_BYTES>>>(
        obs, W1, b1, W21, b21, W22, b22, W31, b31, W32, b32, out, B);
}

// round 3
// speedup vs baseline: 2.6459x; 2.0339x over previous
#include <cuda_runtime.h>

// ---------------------------------------------------------------------------
// BarrierNet fused MLP + CBF filter — v3.
//  * W2 kept SCALAR in smem; phase-B accumulators hold (k,k+1) f32x2 pairs per
//    row, x is register-duplicated. Weight LDS are warp-broadcast.
//  * X tile chunked over j (2 x 64) -> smem 110KB -> 2 CTAs/SM (16 warps).
// ---------------------------------------------------------------------------

typedef unsigned long long u64;

__device__ __forceinline__ u64 pk2(float lo, float hi) {
    u64 r; asm("mov.b64 %0, {%1, %2};" : "=l"(r) : "f"(lo), "f"(hi)); return r;
}
__device__ __forceinline__ void upk2(u64 v, float& lo, float& hi) {
    asm("mov.b64 {%0, %1}, %2;" : "=f"(lo), "=f"(hi) : "l"(v));
}
__device__ __forceinline__ u64 fma2(u64 a, u64 b, u64 c) {
    u64 d; asm("fma.rn.f32x2 %0, %1, %2, %3;" : "=l"(d) : "l"(a), "l"(b), "l"(c)); return d;
}
__device__ __forceinline__ u64 dup2(float w) { return pk2(w, w); }

__device__ __forceinline__ float fast_silu(float z) {
    return __fdividef(z, 1.0f + __expf(-z));
}
__device__ __forceinline__ float fast_sigmoid(float z) {
    return __fdividef(1.0f, 1.0f + __expf(-z));
}

// ---- shared memory layout (u64 units) ----
#define OFF_W1D  0        // [128 j][10 f] dup u64        (1280)
#define OFF_B1D  1280     // [128] dup                    (128)
#define OFF_B2   1408     // f32[64] scalar (b21|b22)     (32)
#define OFF_W31  1440     // f32[64] scalar ([2][32])     (32)
#define OFF_W32  1472     // f32[32] scalar               (16)
#define OFF_SCAL 1488     // f32: b31x, b31y, b32         (2)
#define OFF_W2   1504     // f32[128 j][64 k] scalar      (4096)
#define OFF_X2   5600     // [64 jloc][128 packs] u64     (8192)
#define OFF_H2   1504     // alias W2+X2: [256 rows][33]  (8448 <= 12288)
#define SMEM_U64 13792
#define SMEM_BYTES (SMEM_U64 * 8)   // 110336 B -> 2 CTAs/SM

__device__ __forceinline__ void cbf_project(
    float u0, float u1, float alpha_pre,
    float rx, float ry, float vhx, float vhy,
    float& ox, float& oy)
{
    float alpha   = 4.0f * fast_sigmoid(alpha_pre);
    float barrier = rx * rx + ry * ry - 0.64f;          // R_SAFE^2
    float lf      = -2.0f * (rx * vhx + ry * vhy);
    float Gx = -2.0f * rx, Gy = -2.0f * ry;
    float h    = lf + alpha * barrier;
    float gg   = Gx * Gx + Gy * Gy;
    float viol = Gx * u0 + Gy * u1 - h;
    float lam  = (gg > 0.0f)
        ? __fdividef(fmaxf(viol, 0.0f), fmaxf(gg, 1e-12f))
        : 0.0f;
    ox = u0 - lam * Gx;
    oy = u1 - lam * Gy;
}

__global__ void __launch_bounds__(256, 2)
barriernet_kernel(const float* __restrict__ obs,
                  const float* __restrict__ W1,  const float* __restrict__ b1,
                  const float* __restrict__ W21, const float* __restrict__ b21,
                  const float* __restrict__ W22, const float* __restrict__ b22,
                  const float* __restrict__ W31, const float* __restrict__ b31,
                  const float* __restrict__ W32, const float* __restrict__ b32,
                  float* __restrict__ out, int B)
{
    extern __shared__ u64 sm[];
    const int tid = threadIdx.x;

    float* w2f   = reinterpret_cast<float*>(sm + OFF_W2);
    float* b2f   = reinterpret_cast<float*>(sm + OFF_B2);
    float* w31f  = reinterpret_cast<float*>(sm + OFF_W31);
    float* w32f  = reinterpret_cast<float*>(sm + OFF_W32);
    float* scalf = reinterpret_cast<float*>(sm + OFF_SCAL);

    // ---------------- weight staging ----------------
    for (int i = tid; i < 1280; i += 256) sm[OFF_W1D + i] = dup2(W1[i]);
    for (int i = tid; i < 128; i += 256)  sm[OFF_B1D + i] = dup2(b1[i]);
    if (tid < 64) {
        b2f[tid]  = (tid < 32) ? b21[tid] : b22[tid - 32];
        w31f[tid] = W31[tid];                  // [2][32] row-major
    }
    if (tid < 32) w32f[tid] = W32[tid];
    if (tid == 0) { scalf[0] = b31[0]; scalf[1] = b31[1]; scalf[2] = b32[0]; }
    for (int i = tid; i < 8192; i += 256) {    // W2 scalar [j][k]
        int j = i >> 6, k = i & 63;
        w2f[i] = (k < 32) ? W21[k * 128 + j] : W22[(k - 32) * 128 + j];
    }
    __syncthreads();

    const long long row_base = (long long)blockIdx.x * 256;

    // phase-B thread mapping
    const int kq = tid >> 6;          // 0..3 : k0 = 16*kq (8 k-pairs)
    const int ph = (tid >> 5) & 1;    // pack half
    const int rg = tid & 31;
    const int k0 = kq * 16;

    // accumulators: acc[r][i] = (k0+2i, k0+2i+1) pair for row (ph*128+4rg+r)
    u64 acc[4][8];
    {
        const u64* b2p = sm + OFF_B2;   // native (k,k+1) pairs
        #pragma unroll
        for (int i = 0; i < 8; i++) {
            u64 b = b2p[kq * 8 + i];
            acc[0][i] = b; acc[1][i] = b; acc[2][i] = b; acc[3][i] = b;
        }
    }

    // phase-A thread mapping
    const int rp = tid & 127;         // pack id
    const int jg = tid >> 7;          // 0..1

    #pragma unroll 1
    for (int c = 0; c < 2; c++) {
        // ---------- Phase A: x[jloc][pack] for j in [c*64, c*64+64) ----------
        {
            const long long r0 = row_base + 2 * rp;
            u64 o[10];
            if (r0 < B) {
                const float4* op = reinterpret_cast<const float4*>(obs + r0 * 10);
                float4 q0 = op[0], q1 = op[1], q2 = op[2], q3 = op[3], q4 = op[4];
                o[0] = pk2(q0.x, q2.z); o[1] = pk2(q0.y, q2.w);
                o[2] = pk2(q0.z, q3.x); o[3] = pk2(q0.w, q3.y);
                o[4] = pk2(q1.x, q3.z); o[5] = pk2(q1.y, q3.w);
                o[6] = pk2(q1.z, q4.x); o[7] = pk2(q1.w, q4.y);
                o[8] = pk2(q2.x, q4.z); o[9] = pk2(q2.y, q4.w);
            } else {
                #pragma unroll
                for (int f = 0; f < 10; f++) o[f] = 0ull;
            }
            const int jbase = c * 64 + jg * 32;
            #pragma unroll 2
            for (int jj = 0; jj < 32; jj++) {
                const u64* w = sm + OFF_W1D + (jbase + jj) * 10;
                u64 z = sm[OFF_B1D + jbase + jj];
                #pragma unroll
                for (int f = 0; f < 10; f++) z = fma2(o[f], w[f], z);
                float zl, zh; upk2(z, zl, zh);
                sm[OFF_X2 + (jg * 32 + jj) * 128 + rp] =
                    pk2(fast_silu(zl), fast_silu(zh));
            }
        }
        __syncthreads();

        // ---------- Phase B: accumulate 64 j's ----------
        {
            const ulonglong2* xbase = reinterpret_cast<const ulonglong2*>(sm + OFF_X2);
            #pragma unroll 2
            for (int jl = 0; jl < 64; jl++) {
                // x: packs {ph*64+2rg, ph*64+2rg+1} -> rows ph*128+4rg .. +3
                ulonglong2 xa = xbase[jl * 64 + ph * 32 + rg];
                float x0, x1, x2, x3;
                upk2(xa.x, x0, x1); upk2(xa.y, x2, x3);
                u64 xd0 = dup2(x0), xd1 = dup2(x1), xd2 = dup2(x2), xd3 = dup2(x3);

                // w: 16 scalars k0..k0+15 as 8 native (k,k+1) pairs (broadcast)
                const ulonglong2* wp = reinterpret_cast<const ulonglong2*>(
                    w2f + (c * 64 + jl) * 64 + k0);
                ulonglong2 wa = wp[0], wb = wp[1], wc = wp[2], wd = wp[3];
                u64 w[8] = { wa.x, wa.y, wb.x, wb.y, wc.x, wc.y, wd.x, wd.y };

                #pragma unroll
                for (int i = 0; i < 8; i++) {
                    acc[0][i] = fma2(xd0, w[i], acc[0][i]);
                    acc[1][i] = fma2(xd1, w[i], acc[1][i]);
                    acc[2][i] = fma2(xd2, w[i], acc[2][i]);
                    acc[3][i] = fma2(xd3, w[i], acc[3][i]);
                }
            }
        }
        __syncthreads();   // X2 (and after c=1, W2) free for reuse
    }

    // ---------- silu(hidden) -> h2[row][33] (u64 (k,k+1) pairs) ----------
    {
        const int rowb = ph * 128 + 4 * rg;
        #pragma unroll
        for (int r = 0; r < 4; r++) {
            u64* h = sm + OFF_H2 + (rowb + r) * 33 + kq * 8;
            #pragma unroll
            for (int i = 0; i < 8; i++) {
                float a, b; upk2(acc[r][i], a, b);
                h[i] = pk2(fast_silu(a), fast_silu(b));
            }
        }
    }
    __syncthreads();

    // ---------- Phase C: heads + CBF (one row per thread) ----------
    {
        const long long r0 = row_base + tid;
        if (r0 < B) {
            const u64* h = sm + OFF_H2 + tid * 33;
            float u0 = scalf[0], u1 = scalf[1], aw = scalf[2];
            #pragma unroll
            for (int kk = 0; kk < 16; kk++) {
                float a, b; upk2(h[kk], a, b);
                u0 += a * w31f[2 * kk]      + b * w31f[2 * kk + 1];
                u1 += a * w31f[32 + 2 * kk] + b * w31f[32 + 2 * kk + 1];
            }
            #pragma unroll
            for (int kk = 0; kk < 16; kk++) {
                float a, b; upk2(h[16 + kk], a, b);
                aw += a * w32f[2 * kk] + b * w32f[2 * kk + 1];
            }
            const float2* p0 = reinterpret_cast<const float2*>(obs + r0 * 10 + 6);
            float2 rv = p0[0], vv = p0[1];
            float ox, oy;
            cbf_project(u0, u1, aw, rv.x, rv.y, vv.x, vv.y, ox, oy);
            reinterpret_cast<float2*>(out)[r0] = make_float2(ox, oy);
        }
    }
}

extern "C" void kernel_launch(void* const* d_in, const int* in_sizes, int n_in,
                              void* d_out, int out_size)
{
    const float* obs = (const float*)d_in[0];
    const float* W1  = (const float*)d_in[1];
    const float* b1  = (const float*)d_in[2];
    const float* W21 = (const float*)d_in[3];
    const float* b21 = (const float*)d_in[4];
    const float* W22 = (const float*)d_in[5];
    const float* b22 = (const float*)d_in[6];
    const float* W31 = (const float*)d_in[7];
    const float* b31 = (const float*)d_in[8];
    const float* W32 = (const float*)d_in[9];
    const float* b32 = (const float*)d_in[10];
    float* out = (float*)d_out;

    int B = in_sizes[0] / 10;

    cudaFuncSetAttribute(barriernet_kernel,
                         cudaFuncAttributeMaxDynamicSharedMemorySize, SMEM_BYTES);

    int blocks = (B + 255) / 256;
    barriernet_kernel<<<blocks, 256, SMEM_BYTES>>>(
        obs, W1, b1, W21, b21, W22, b22, W31, b31, W32, b32, out, B);
}

// round 5
// speedup vs baseline: 2.8143x; 1.0637x over previous
#include <cuda_runtime.h>
#include <cuda_bf16.h>
#include <cstdint>

// ---------------------------------------------------------------------------
// BarrierNet — mma.sync (legacy HMMA, baseline PTX) split-bf16 version.
//   Layer1 (10->128): fp32 FFMA2 per-thread (row pairs (r, r+64) packed),
//                     silu, split into bf16 hi/lo, STS to swizzled [row][k].
//   Layer2 (128->64): warp-tile mma.sync.m16n8k16.bf16, fp32 acc in regs,
//                     3 passes: AhiBhi + AloBhi + AhiBlo.
//   Epilogue        : bias+silu+heads on D fragment, shfl quad-reduce, CBF.
//   CTA = 256 thr, processes 256 rows as two 128-row halves. 2 CTAs/SM.
// ---------------------------------------------------------------------------

typedef unsigned long long u64;
typedef unsigned int u32;

// smem byte offsets
#define SM_XHI   0        // bf16 x_hi  [128 rows][128 k]  (256B/row, swizzled)
#define SM_XLO   32768
#define SM_WHI   65536    // bf16 W2_hi [64 n][128 k]
#define SM_WLO   81920
#define SM_W1D   98304    // u64 dup W1 [128][10]
#define SM_B1D   108544   // u64 dup b1 [128]
#define SM_B2    109568   // f32 [64]  (b21|b22)
#define SM_W31   109824   // f32 [64]  ([2][32])
#define SM_W32   110080   // f32 [32]
#define SM_SCAL  110208   // f32 b31x, b31y, b32
#define SMEM_BYTES 110336

static __device__ __forceinline__ u32 smem_u32(const void* p) {
    u32 a;
    asm("{ .reg .u64 t; cvta.to.shared.u64 t, %1; cvt.u32.u64 %0, t; }"
        : "=r"(a) : "l"(p));
    return a;
}
static __device__ __forceinline__ u64 pk2(float lo, float hi) {
    u64 r; asm("mov.b64 %0, {%1, %2};" : "=l"(r) : "f"(lo), "f"(hi)); return r;
}
static __device__ __forceinline__ void upk2(u64 v, float& lo, float& hi) {
    asm("mov.b64 {%0, %1}, %2;" : "=f"(lo), "=f"(hi) : "l"(v));
}
static __device__ __forceinline__ u64 fma2(u64 a, u64 b, u64 c) {
    u64 d; asm("fma.rn.f32x2 %0, %1, %2, %3;" : "=l"(d) : "l"(a), "l"(b), "l"(c)); return d;
}
static __device__ __forceinline__ u64 dup2(float w) { return pk2(w, w); }

static __device__ __forceinline__ float fast_silu(float z) {
    return __fdividef(z, 1.0f + __expf(-z));
}
static __device__ __forceinline__ float fast_sigmoid(float z) {
    return __fdividef(1.0f, 1.0f + __expf(-z));
}
static __device__ __forceinline__ void split_bf(float s, u32& h, u32& l) {
    __nv_bfloat16 hb = __float2bfloat16(s);
    __nv_bfloat16 lb = __float2bfloat16(s - __bfloat162float(hb));
    h = (u32)__bfloat16_as_ushort(hb);
    l = (u32)__bfloat16_as_ushort(lb);
}

static __device__ __forceinline__ void ldsm4(u32* r, u32 addr) {
    asm volatile("ldmatrix.sync.aligned.m8n8.x4.shared.b16 {%0,%1,%2,%3}, [%4];"
        : "=r"(r[0]), "=r"(r[1]), "=r"(r[2]), "=r"(r[3]) : "r"(addr));
}
static __device__ __forceinline__ void mma_bf16(float* d, const u32* a, u32 b0, u32 b1) {
    asm volatile("mma.sync.aligned.m16n8k16.row.col.f32.bf16.bf16.f32 "
        "{%0,%1,%2,%3}, {%4,%5,%6,%7}, {%8,%9}, {%0,%1,%2,%3};"
        : "+f"(d[0]), "+f"(d[1]), "+f"(d[2]), "+f"(d[3])
        : "r"(a[0]), "r"(a[1]), "r"(a[2]), "r"(a[3]), "r"(b0), "r"(b1));
}

__global__ void __launch_bounds__(256, 2)
barriernet_kernel(const float* __restrict__ obs,
                  const float* __restrict__ W1,  const float* __restrict__ b1,
                  const float* __restrict__ W21, const float* __restrict__ b21,
                  const float* __restrict__ W22, const float* __restrict__ b22,
                  const float* __restrict__ W31, const float* __restrict__ b31,
                  const float* __restrict__ W32, const float* __restrict__ b32,
                  float* __restrict__ out, int B)
{
    extern __shared__ char smc[];
    const u32 smb = smem_u32(smc);
    const int tid = threadIdx.x;

    u64*   w1d  = reinterpret_cast<u64*>(smc + SM_W1D);
    u64*   b1d  = reinterpret_cast<u64*>(smc + SM_B1D);
    float* b2f  = reinterpret_cast<float*>(smc + SM_B2);
    float* w31f = reinterpret_cast<float*>(smc + SM_W31);
    float* w32f = reinterpret_cast<float*>(smc + SM_W32);
    float* scal = reinterpret_cast<float*>(smc + SM_SCAL);

    // ------------------------------ staging ------------------------------
    for (int i = tid; i < 1280; i += 256) w1d[i] = dup2(W1[i]);
    if (tid < 128) b1d[tid] = dup2(b1[tid]);
    if (tid < 64) {
        b2f[tid]  = (tid < 32) ? b21[tid] : b22[tid - 32];
        w31f[tid] = W31[tid];                       // [2][32] row-major
    }
    if (tid < 32) w32f[tid] = W32[tid];
    if (tid == 0) { scal[0] = b31[0]; scal[1] = b31[1]; scal[2] = b32[0]; }

    // W2 = [W21 ; W22] as [n][k] bf16 hi/lo, 256B rows, XOR-swizzled
    for (int i = tid; i < 4096; i += 256) {
        int n = i >> 6, kp = i & 63;                // k = 2kp, 2kp+1
        const float* src = (n < 32) ? (W21 + n * 128 + 2 * kp)
                                    : (W22 + (n - 32) * 128 + 2 * kp);
        float2 w = *reinterpret_cast<const float2*>(src);
        u32 h0, l0, h1, l1;
        split_bf(w.x, h0, l0);
        split_bf(w.y, h1, l1);
        u32 off = (u32)(n * 256) + (((u32)(4 * kp)) ^ ((u32)(n & 7) << 4));
        *reinterpret_cast<u32*>(smc + SM_WHI + off) = h0 | (h1 << 16);
        *reinterpret_cast<u32*>(smc + SM_WLO + off) = l0 | (l1 << 16);
    }
    __syncthreads();

    const long long row_base = (long long)blockIdx.x * 256;

    // -------- phase-A mapping: pack p -> local rows (p, p+64) --------
    const int p  = tid & 63;
    const int jq = tid >> 6;        // j in [32*jq, 32*jq+32)

    // -------- mma mapping --------
    const int wid  = tid >> 5, lane = tid & 31;
    const int gid  = lane >> 2, tig = lane & 3;
    const int g8   = lane >> 3, r8  = lane & 7;
    const int mr   = wid * 16;                       // warp's m-tile base row
    const u32 swz  = (u32)r8 << 4;
    const u32 a_row   = (u32)(mr + ((g8 & 1) << 3) + r8);
    const u32 a_koff  = (u32)((g8 >> 1) << 4);
    const u32 aHbase  = smb + SM_XHI + a_row * 256;
    const u32 aLbase  = smb + SM_XLO + a_row * 256;
    const u32 b_noff  = (u32)(((g8 >> 1) << 3) + r8);
    const u32 b_koff  = (u32)((g8 & 1) << 4);
    u32 bHb[4], bLb[4];
    #pragma unroll
    for (int g = 0; g < 4; g++) {
        u32 n = (u32)(g * 16) + b_noff;
        bHb[g] = smb + SM_WHI + n * 256;
        bLb[g] = smb + SM_WLO + n * 256;
    }

    #pragma unroll 1
    for (int h = 0; h < 2; h++) {
        // ======================= Phase A =======================
        {
            const long long ga = row_base + h * 128 + p;
            const long long gb = ga + 64;
            float av[10], bv[10];
            if (ga < B) {
                const float2* q = reinterpret_cast<const float2*>(obs + ga * 10);
                #pragma unroll
                for (int f = 0; f < 5; f++) { float2 v = q[f]; av[2*f] = v.x; av[2*f+1] = v.y; }
            } else {
                #pragma unroll
                for (int f = 0; f < 10; f++) av[f] = 0.f;
            }
            if (gb < B) {
                const float2* q = reinterpret_cast<const float2*>(obs + gb * 10);
                #pragma unroll
                for (int f = 0; f < 5; f++) { float2 v = q[f]; bv[2*f] = v.x; bv[2*f+1] = v.y; }
            } else {
                #pragma unroll
                for (int f = 0; f < 10; f++) bv[f] = 0.f;
            }
            u64 od[10];
            #pragma unroll
            for (int f = 0; f < 10; f++) od[f] = pk2(av[f], bv[f]);

            const u32 rA = (u32)p, rB = (u32)(p + 64);
            const u32 swA = ((u32)(rA & 7)) << 4;   // == (rB&7)<<4
            #pragma unroll 1
            for (int blk = 0; blk < 4; blk++) {
                u32 hA[4], lA[4], hB[4], lB[4];
                #pragma unroll
                for (int q = 0; q < 8; q++) {
                    const int j = jq * 32 + blk * 8 + q;
                    const u64* w = w1d + j * 10;
                    u64 z = b1d[j];
                    #pragma unroll
                    for (int f = 0; f < 10; f++) z = fma2(od[f], w[f], z);
                    float za, zb; upk2(z, za, zb);
                    float sa = fast_silu(za), sb = fast_silu(zb);
                    u32 ha, la, hb, lb;
                    split_bf(sa, ha, la);
                    split_bf(sb, hb, lb);
                    const int idx = q >> 1;
                    if (q & 1) {
                        hA[idx] |= ha << 16; lA[idx] |= la << 16;
                        hB[idx] |= hb << 16; lB[idx] |= lb << 16;
                    } else {
                        hA[idx] = ha; lA[idx] = la;
                        hB[idx] = hb; lB[idx] = lb;
                    }
                }
                const u32 kb = (u32)(jq * 64 + blk * 16);
                const u32 offA = rA * 256 + (kb ^ swA);
                const u32 offB = rB * 256 + (kb ^ swA);
                *reinterpret_cast<uint4*>(smc + SM_XHI + offA) = make_uint4(hA[0], hA[1], hA[2], hA[3]);
                *reinterpret_cast<uint4*>(smc + SM_XLO + offA) = make_uint4(lA[0], lA[1], lA[2], lA[3]);
                *reinterpret_cast<uint4*>(smc + SM_XHI + offB) = make_uint4(hB[0], hB[1], hB[2], hB[3]);
                *reinterpret_cast<uint4*>(smc + SM_XLO + offB) = make_uint4(lB[0], lB[1], lB[2], lB[3]);
            }
        }
        __syncthreads();

        // ======================= MMA (per warp: 16 rows x 64 n) =======================
        float acc[8][4];
        #pragma unroll
        for (int nt = 0; nt < 8; nt++)
            #pragma unroll
            for (int c = 0; c < 4; c++) acc[nt][c] = 0.f;

        #pragma unroll 1
        for (int ks = 0; ks < 8; ks++) {
            const u32 kbyte = (u32)(32 * ks);
            const u32 ka = (kbyte + a_koff) ^ swz;
            const u32 kb = (kbyte + b_koff) ^ swz;
            u32 ah[4], al[4], bb[4][4];
            ldsm4(ah, aHbase + ka);
            ldsm4(al, aLbase + ka);
            #pragma unroll
            for (int g = 0; g < 4; g++) ldsm4(bb[g], bHb[g] + kb);
            #pragma unroll
            for (int nt = 0; nt < 8; nt++) {
                u32 b0 = bb[nt >> 1][(nt & 1) * 2];
                u32 b1v = bb[nt >> 1][(nt & 1) * 2 + 1];
                mma_bf16(acc[nt], ah, b0, b1v);
                mma_bf16(acc[nt], al, b0, b1v);
            }
            #pragma unroll
            for (int g = 0; g < 4; g++) ldsm4(bb[g], bLb[g] + kb);
            #pragma unroll
            for (int nt = 0; nt < 8; nt++) {
                u32 b0 = bb[nt >> 1][(nt & 1) * 2];
                u32 b1v = bb[nt >> 1][(nt & 1) * 2 + 1];
                mma_bf16(acc[nt], ah, b0, b1v);
            }
        }

        // ======================= Epilogue =======================
        {
            float s0a = 0.f, s1a = 0.f, s2a = 0.f;   // row mr+gid
            float s0b = 0.f, s1b = 0.f, s2b = 0.f;   // row mr+8+gid
            #pragma unroll
            for (int nt = 0; nt < 8; nt++) {
                #pragma unroll
                for (int c = 0; c < 2; c++) {
                    const int col = nt * 8 + 2 * tig + c;
                    const float bias = b2f[col];
                    const float v0 = fast_silu(acc[nt][c] + bias);
                    const float v1 = fast_silu(acc[nt][2 + c] + bias);
                    if (nt < 4) {
                        const float wA = w31f[col], wB = w31f[32 + col];
                        s0a += v0 * wA; s1a += v0 * wB;
                        s0b += v1 * wA; s1b += v1 * wB;
                    } else {
                        const float wC = w32f[col - 32];
                        s2a += v0 * wC; s2b += v1 * wC;
                    }
                }
            }
            #pragma unroll
            for (int m = 1; m <= 2; m <<= 1) {
                s0a += __shfl_xor_sync(0xFFFFFFFFu, s0a, m);
                s1a += __shfl_xor_sync(0xFFFFFFFFu, s1a, m);
                s2a += __shfl_xor_sync(0xFFFFFFFFu, s2a, m);
                s0b += __shfl_xor_sync(0xFFFFFFFFu, s0b, m);
                s1b += __shfl_xor_sync(0xFFFFFFFFu, s1b, m);
                s2b += __shfl_xor_sync(0xFFFFFFFFu, s2b, m);
            }
            if (tig < 2) {
                const int rloc = mr + gid + (tig ? 8 : 0);
                const long long grow = row_base + h * 128 + rloc;
                if (grow < B) {
                    const float u0 = (tig ? s0b : s0a) + scal[0];
                    const float u1 = (tig ? s1b : s1a) + scal[1];
                    const float aw = (tig ? s2b : s2a) + scal[2];
                    const float2* pp = reinterpret_cast<const float2*>(obs + grow * 10 + 6);
                    const float2 rv = pp[0], vv = pp[1];
                    const float alpha   = 4.0f * fast_sigmoid(aw);
                    const float barrier = rv.x * rv.x + rv.y * rv.y - 0.64f;
                    const float lf      = -2.0f * (rv.x * vv.x + rv.y * vv.y);
                    const float Gx = -2.0f * rv.x, Gy = -2.0f * rv.y;
                    const float hh   = lf + alpha * barrier;
                    const float gg   = Gx * Gx + Gy * Gy;
                    const float viol = Gx * u0 + Gy * u1 - hh;
                    const float lam  = (gg > 0.0f)
                        ? __fdividef(fmaxf(viol, 0.0f), fmaxf(gg, 1e-12f))
                        : 0.0f;
                    reinterpret_cast<float2*>(out)[grow] =
                        make_float2(u0 - lam * Gx, u1 - lam * Gy);
                }
            }
        }
        __syncthreads();
    }
}

extern "C" void kernel_launch(void* const* d_in, const int* in_sizes, int n_in,
                              void* d_out, int out_size)
{
    const float* obs = (const float*)d_in[0];
    const float* W1  = (const float*)d_in[1];
    const float* b1  = (const float*)d_in[2];
    const float* W21 = (const float*)d_in[3];
    const float* b21 = (const float*)d_in[4];
    const float* W22 = (const float*)d_in[5];
    const float* b22 = (const float*)d_in[6];
    const float* W31 = (const float*)d_in[7];
    const float* b31 = (const float*)d_in[8];
    const float* W32 = (const float*)d_in[9];
    const float* b32 = (const float*)d_in[10];
    float* out = (float*)d_out;

    int B = in_sizes[0] / 10;

    cudaFuncSetAttribute(barriernet_kernel,
                         cudaFuncAttributeMaxDynamicSharedMemorySize, SMEM_BYTES);

    int blocks = (B + 255) / 256;
    barriernet_kernel<<<blocks, 256, SMEM_BYTES>>>(
        obs, W1, b1, W21, b21, W22, b22, W31, b31, W32, b32, out, B);
}

// round 6
// speedup vs baseline: 5.7123x; 2.0297x over previous
#include <cuda_runtime.h>
#include <cuda_bf16.h>
#include <cstdint>

// ---------------------------------------------------------------------------
// BarrierNet — mma.sync split-bf16, high-occupancy version.
//   CTA = 512 threads, 512 rows, four 128-row phases. 2 CTAs/SM = 32 warps.
//   Phase A : layer1 fp32 FFMA2 (j-pairs packed), silu, bf16 hi/lo split via
//             cvt.rn.bf16x2 + shift-residual, STS swizzled [row][k].
//   MMA     : warp = (m-tile, n-half); m16n8k16.bf16 x 3 passes, fp32 acc.
//   Epilogue: bias+silu+heads in regs, quad shfl-reduce, partials -> smem,
//             final 128 threads do CBF + store.
// ---------------------------------------------------------------------------

typedef unsigned long long u64;
typedef unsigned int u32;

#define SM_XHI   0        // 128 rows x 256B
#define SM_XLO   32768
#define SM_WHI   65536    // 64 n x 256B
#define SM_WLO   81920
#define SM_W1P   98304    // u64[640]  W1 (j,j+1) pairs
#define SM_B1P   103424   // u64[64]
#define SM_B2    103936   // f32[64]
#define SM_W31   104192   // f32[64]
#define SM_W32   104448   // f32[32]
#define SM_SCAL  104576   // f32[4]
#define SM_U01   104592   // float2[128]
#define SM_AW    105616   // float[128]
#define SMEM_BYTES 106128

static __device__ __forceinline__ u32 smem_u32(const void* p) {
    u32 a;
    asm("{ .reg .u64 t; cvta.to.shared.u64 t, %1; cvt.u32.u64 %0, t; }"
        : "=r"(a) : "l"(p));
    return a;
}
static __device__ __forceinline__ u64 pk2(float lo, float hi) {
    u64 r; asm("mov.b64 %0, {%1, %2};" : "=l"(r) : "f"(lo), "f"(hi)); return r;
}
static __device__ __forceinline__ void upk2(u64 v, float& lo, float& hi) {
    asm("mov.b64 {%0, %1}, %2;" : "=f"(lo), "=f"(hi) : "l"(v));
}
static __device__ __forceinline__ u64 fma2(u64 a, u64 b, u64 c) {
    u64 d; asm("fma.rn.f32x2 %0, %1, %2, %3;" : "=l"(d) : "l"(a), "l"(b), "l"(c)); return d;
}
static __device__ __forceinline__ u64 dup2(float w) { return pk2(w, w); }

static __device__ __forceinline__ float fast_silu(float z) {
    return __fdividef(z, 1.0f + __expf(-z));
}
static __device__ __forceinline__ float fast_sigmoid(float z) {
    return __fdividef(1.0f, 1.0f + __expf(-z));
}
// pack (hi -> upper 16, lo -> lower 16)
static __device__ __forceinline__ u32 cvt_bf16x2(float hi, float lo) {
    u32 d; asm("cvt.rn.bf16x2.f32 %0, %1, %2;" : "=r"(d) : "f"(hi), "f"(lo));
    return d;
}
// hi/lo split of two floats -> packed hi u32, packed lo u32 (lower = s0)
static __device__ __forceinline__ void split2(float s0, float s1, u32& h, u32& l) {
    h = cvt_bf16x2(s1, s0);
    float f0 = __uint_as_float(h << 16);
    float f1 = __uint_as_float(h & 0xFFFF0000u);
    l = cvt_bf16x2(s1 - f1, s0 - f0);
}

static __device__ __forceinline__ void ldsm4(u32* r, u32 addr) {
    asm volatile("ldmatrix.sync.aligned.m8n8.x4.shared.b16 {%0,%1,%2,%3}, [%4];"
        : "=r"(r[0]), "=r"(r[1]), "=r"(r[2]), "=r"(r[3]) : "r"(addr));
}
static __device__ __forceinline__ void mma_bf16(float* d, const u32* a, u32 b0, u32 b1) {
    asm volatile("mma.sync.aligned.m16n8k16.row.col.f32.bf16.bf16.f32 "
        "{%0,%1,%2,%3}, {%4,%5,%6,%7}, {%8,%9}, {%0,%1,%2,%3};"
        : "+f"(d[0]), "+f"(d[1]), "+f"(d[2]), "+f"(d[3])
        : "r"(a[0]), "r"(a[1]), "r"(a[2]), "r"(a[3]), "r"(b0), "r"(b1));
}

__global__ void __launch_bounds__(512, 2)
barriernet_kernel(const float* __restrict__ obs,
                  const float* __restrict__ W1,  const float* __restrict__ b1,
                  const float* __restrict__ W21, const float* __restrict__ b21,
                  const float* __restrict__ W22, const float* __restrict__ b22,
                  const float* __restrict__ W31, const float* __restrict__ b31,
                  const float* __restrict__ W32, const float* __restrict__ b32,
                  float* __restrict__ out, int B)
{
    extern __shared__ char smc[];
    const u32 smb = smem_u32(smc);
    const int tid = threadIdx.x;

    u64*    w1p  = reinterpret_cast<u64*>(smc + SM_W1P);
    u64*    b1p  = reinterpret_cast<u64*>(smc + SM_B1P);
    float*  b2f  = reinterpret_cast<float*>(smc + SM_B2);
    float*  w31f = reinterpret_cast<float*>(smc + SM_W31);
    float*  w32f = reinterpret_cast<float*>(smc + SM_W32);
    float*  scal = reinterpret_cast<float*>(smc + SM_SCAL);
    float2* u01  = reinterpret_cast<float2*>(smc + SM_U01);
    float*  awb  = reinterpret_cast<float*>(smc + SM_AW);

    // ------------------------------ staging ------------------------------
    for (int i = tid; i < 640; i += 512) {
        int jp = i / 10, f = i - jp * 10;
        w1p[i] = pk2(W1[(2 * jp) * 10 + f], W1[(2 * jp + 1) * 10 + f]);
    }
    if (tid < 64) {
        b1p[tid]  = pk2(b1[2 * tid], b1[2 * tid + 1]);
        b2f[tid]  = (tid < 32) ? b21[tid] : b22[tid - 32];
        w31f[tid] = W31[tid];                       // [2][32] row-major
    }
    if (tid < 32) w32f[tid] = W32[tid];
    if (tid == 0) { scal[0] = b31[0]; scal[1] = b31[1]; scal[2] = b32[0]; }

    for (int i = tid; i < 4096; i += 512) {
        int n = i >> 6, kp = i & 63;                // elems k = 2kp, 2kp+1
        const float* src = (n < 32) ? (W21 + n * 128 + 2 * kp)
                                    : (W22 + (n - 32) * 128 + 2 * kp);
        float2 w = *reinterpret_cast<const float2*>(src);
        u32 h, l;
        split2(w.x, w.y, h, l);
        u32 off = (u32)(n * 256) + (((u32)(4 * kp)) ^ ((u32)(n & 7) << 4));
        *reinterpret_cast<u32*>(smc + SM_WHI + off) = h;
        *reinterpret_cast<u32*>(smc + SM_WLO + off) = l;
    }
    __syncthreads();

    const long long row_base = (long long)blockIdx.x * 512;

    // -------- phase-A mapping: row = tid&127, j-group = tid>>7 --------
    const int prow = tid & 127;
    const int jq   = tid >> 7;          // 16 j-pairs starting at jq*16

    // -------- mma mapping --------
    const int wid = tid >> 5, lane = tid & 31;
    const int gid = lane >> 2, tig = lane & 3;
    const int g8  = lane >> 3, r8 = lane & 7;
    const int mtile = wid & 7, nh = wid >> 3;
    const int mr = mtile * 16;
    const u32 swz    = (u32)r8 << 4;
    const u32 a_row  = (u32)(mr + ((g8 & 1) << 3) + r8);
    const u32 a_koff = (u32)((g8 >> 1) << 4);
    const u32 aHbase = smb + SM_XHI + a_row * 256;
    const u32 aLbase = smb + SM_XLO + a_row * 256;
    const u32 b_noff = (u32)(((g8 >> 1) << 3) + r8);
    const u32 b_koff = (u32)((g8 & 1) << 4);
    u32 bHb[2], bLb[2];
    #pragma unroll
    for (int g = 0; g < 2; g++) {
        u32 n = (u32)(nh * 32 + g * 16) + b_noff;
        bHb[g] = smb + SM_WHI + n * 256;
        bLb[g] = smb + SM_WLO + n * 256;
    }

    #pragma unroll 1
    for (int ph = 0; ph < 4; ph++) {
        // ======================= Phase A (128 rows) =======================
        {
            const long long grow = row_base + ph * 128 + prow;
            u64 od[10];
            if (grow < B) {
                const float2* q = reinterpret_cast<const float2*>(obs + grow * 10);
                #pragma unroll
                for (int f = 0; f < 5; f++) {
                    float2 v = q[f];
                    od[2 * f]     = dup2(v.x);
                    od[2 * f + 1] = dup2(v.y);
                }
            } else {
                #pragma unroll
                for (int f = 0; f < 10; f++) od[f] = 0ull;
            }
            const u32 swr = ((u32)(prow & 7)) << 4;
            #pragma unroll 1
            for (int blk = 0; blk < 4; blk++) {
                u32 hi[4], lo[4];
                #pragma unroll
                for (int q = 0; q < 4; q++) {
                    const int jp = jq * 16 + blk * 4 + q;
                    const u64* w = w1p + jp * 10;
                    u64 z = b1p[jp];
                    #pragma unroll
                    for (int f = 0; f < 10; f++) z = fma2(od[f], w[f], z);
                    float z0, z1; upk2(z, z0, z1);
                    split2(fast_silu(z0), fast_silu(z1), hi[q], lo[q]);
                }
                const u32 kb  = (u32)(jq * 64 + blk * 16);
                const u32 off = (u32)prow * 256 + (kb ^ swr);
                *reinterpret_cast<uint4*>(smc + SM_XHI + off) =
                    make_uint4(hi[0], hi[1], hi[2], hi[3]);
                *reinterpret_cast<uint4*>(smc + SM_XLO + off) =
                    make_uint4(lo[0], lo[1], lo[2], lo[3]);
            }
        }
        __syncthreads();

        // ======================= MMA: 16 rows x 32 n per warp =======================
        float acc[4][4];
        #pragma unroll
        for (int nt = 0; nt < 4; nt++)
            #pragma unroll
            for (int c = 0; c < 4; c++) acc[nt][c] = 0.f;

        #pragma unroll 1
        for (int ks = 0; ks < 8; ks++) {
            const u32 kbyte = (u32)(32 * ks);
            const u32 ka = (kbyte + a_koff) ^ swz;
            const u32 kb = (kbyte + b_koff) ^ swz;
            u32 ah[4], al[4], bb[2][4];
            ldsm4(ah, aHbase + ka);
            ldsm4(al, aLbase + ka);
            ldsm4(bb[0], bHb[0] + kb);
            ldsm4(bb[1], bHb[1] + kb);
            #pragma unroll
            for (int nt = 0; nt < 4; nt++) {
                u32 b0 = bb[nt >> 1][(nt & 1) * 2];
                u32 b1v = bb[nt >> 1][(nt & 1) * 2 + 1];
                mma_bf16(acc[nt], ah, b0, b1v);
                mma_bf16(acc[nt], al, b0, b1v);
            }
            ldsm4(bb[0], bLb[0] + kb);
            ldsm4(bb[1], bLb[1] + kb);
            #pragma unroll
            for (int nt = 0; nt < 4; nt++) {
                u32 b0 = bb[nt >> 1][(nt & 1) * 2];
                u32 b1v = bb[nt >> 1][(nt & 1) * 2 + 1];
                mma_bf16(acc[nt], ah, b0, b1v);
            }
        }

        // ---- heads partials (bias + silu + weighted sums) ----
        {
            float sa0 = 0.f, sa1 = 0.f, sb0 = 0.f, sb1 = 0.f;   // nh==0: u0,u1
            #pragma unroll
            for (int nt = 0; nt < 4; nt++) {
                #pragma unroll
                for (int c = 0; c < 2; c++) {
                    const int col = nh * 32 + nt * 8 + 2 * tig + c;
                    const float bias = b2f[col];
                    const float v0 = fast_silu(acc[nt][c] + bias);       // row mr+gid
                    const float v1 = fast_silu(acc[nt][2 + c] + bias);   // row mr+8+gid
                    if (nh == 0) {
                        const float wA = w31f[col], wB = w31f[32 + col];
                        sa0 += v0 * wA; sa1 += v0 * wB;
                        sb0 += v1 * wA; sb1 += v1 * wB;
                    } else {
                        const float wC = w32f[col - 32];
                        sa0 += v0 * wC;
                        sb0 += v1 * wC;
                    }
                }
            }
            #pragma unroll
            for (int m = 1; m <= 2; m <<= 1) {
                sa0 += __shfl_xor_sync(0xFFFFFFFFu, sa0, m);
                sb0 += __shfl_xor_sync(0xFFFFFFFFu, sb0, m);
                if (nh == 0) {
                    sa1 += __shfl_xor_sync(0xFFFFFFFFu, sa1, m);
                    sb1 += __shfl_xor_sync(0xFFFFFFFFu, sb1, m);
                }
            }
            if (tig < 2) {
                const int row = mr + gid + (tig ? 8 : 0);
                if (nh == 0)
                    u01[row] = make_float2(tig ? sb0 : sa0, tig ? sb1 : sa1);
                else
                    awb[row] = tig ? sb0 : sa0;
            }
        }
        __syncthreads();

        // ======================= CBF + store (128 rows) =======================
        if (tid < 128) {
            const long long grow = row_base + ph * 128 + tid;
            if (grow < B) {
                float2 uv = u01[tid];
                const float u0 = uv.x + scal[0];
                const float u1 = uv.y + scal[1];
                const float aw = awb[tid] + scal[2];
                const float2* pp = reinterpret_cast<const float2*>(obs + grow * 10 + 6);
                const float2 rv = pp[0], vv = pp[1];
                const float alpha   = 4.0f * fast_sigmoid(aw);
                const float barrier = rv.x * rv.x + rv.y * rv.y - 0.64f;
                const float lf      = -2.0f * (rv.x * vv.x + rv.y * vv.y);
                const float Gx = -2.0f * rv.x, Gy = -2.0f * rv.y;
                const float hh   = lf + alpha * barrier;
                const float gg   = Gx * Gx + Gy * Gy;
                const float viol = Gx * u0 + Gy * u1 - hh;
                const float lam  = (gg > 0.0f)
                    ? __fdividef(fmaxf(viol, 0.0f), fmaxf(gg, 1e-12f))
                    : 0.0f;
                reinterpret_cast<float2*>(out)[grow] =
                    make_float2(u0 - lam * Gx, u1 - lam * Gy);
            }
        }
    }
}

extern "C" void kernel_launch(void* const* d_in, const int* in_sizes, int n_in,
                              void* d_out, int out_size)
{
    const float* obs = (const float*)d_in[0];
    const float* W1  = (const float*)d_in[1];
    const float* b1  = (const float*)d_in[2];
    const float* W21 = (const float*)d_in[3];
    const float* b21 = (const float*)d_in[4];
    const float* W22 = (const float*)d_in[5];
    const float* b22 = (const float*)d_in[6];
    const float* W31 = (const float*)d_in[7];
    const float* b31 = (const float*)d_in[8];
    const float* W32 = (const float*)d_in[9];
    const float* b32 = (const float*)d_in[10];
    float* out = (float*)d_out;

    int B = in_sizes[0] / 10;

    cudaFuncSetAttribute(barriernet_kernel,
                         cudaFuncAttributeMaxDynamicSharedMemorySize, SMEM_BYTES);

    int blocks = (B + 511) / 512;
    barriernet_kernel<<<blocks, 512, SMEM_BYTES>>>(
        obs, W1, b1, W21, b21, W22, b22, W31, b31, W32, b32, out, B);
}